// round 1
// baseline (speedup 1.0000x reference)
#include <cuda_runtime.h>
#include <cuda_fp16.h>
#include <mma.h>

using namespace nvcuda;

// Problem constants
#define Bv 4
#define Sv 2048
#define Hv 16
#define DKv 128
#define DMv 2048
#define Mv (Bv * Sv)  // 8192

// ---------------- device scratch (static, allocation-free) ----------------
__device__ __half g_Xh [Mv * DMv];
__device__ __half g_Wqh[DMv * DMv];
__device__ __half g_Wkh[DMv * DMv];
__device__ __half g_Wvh[DMv * DMv];
__device__ __half g_Woh[DMv * DMv];
__device__ float  g_Y  [Mv * DMv];
__device__ __half g_Q  [Mv * DMv];
__device__ __half g_K  [Mv * DMv];
__device__ __half g_V  [Mv * DMv];
__device__ __half g_Ch [Mv * DMv];
__device__ __half g_Cl [Mv * DMv];

// ---------------- fp32 -> fp16 convert ----------------
__global__ void f2h_kernel(const float* __restrict__ in, __half* __restrict__ out, int n) {
    int i = blockIdx.x * blockDim.x + threadIdx.x;
    int stride = gridDim.x * blockDim.x;
    for (; i < n; i += stride) out[i] = __float2half(in[i]);
}

// ---------------- split heads: [B*S, DM] f32 -> [B,H,S,DK] f16 ----------------
__global__ void split_heads_kernel(const float* __restrict__ Y, __half* __restrict__ O) {
    const int n = Mv * DMv;
    int i = blockIdx.x * blockDim.x + threadIdx.x;
    int stride = gridDim.x * blockDim.x;
    for (; i < n; i += stride) {
        int d = i & (DKv - 1);
        int s = (i >> 7) & (Sv - 1);
        int h = (i >> 18) & (Hv - 1);
        int b = i >> 22;
        O[i] = __float2half(Y[((b * Sv + s) << 11) + (h << 7) + d]);
    }
}

// ---------------- GEMM: C[M,N] = A[M,K] * B[N,K]^T, fp16 in / fp32 out ----------------
// 128x128 block tile, 8 warps (2x4), warp tile 64x32, k-step 32.
#define GK 32
#define ASTR 40  // 32 + 8 halves pad

template <bool ACCUM>
__global__ __launch_bounds__(256) void gemm_nt_kernel(
    const __half* __restrict__ A, const __half* __restrict__ Bw,
    float* __restrict__ C, int Mdim, int Ndim, int Kdim) {
    __shared__ __half As[128 * ASTR];
    __shared__ __half Bs[128 * ASTR];

    const int bm = blockIdx.y * 128;
    const int bn = blockIdx.x * 128;
    const int tid  = threadIdx.x;
    const int warp = tid >> 5;
    const int wr = warp >> 2;   // 0..1
    const int wc = warp & 3;    // 0..3

    wmma::fragment<wmma::accumulator, 16, 16, 16, float> acc[4][2];
#pragma unroll
    for (int i = 0; i < 4; i++)
#pragma unroll
        for (int j = 0; j < 2; j++) wmma::fill_fragment(acc[i][j], 0.0f);

    for (int k0 = 0; k0 < Kdim; k0 += GK) {
#pragma unroll
        for (int t = 0; t < 2; t++) {
            int v = tid + t * 256;          // 0..511
            int r = v >> 2;                 // 0..127
            int c = (v & 3) * 8;            // 0,8,16,24
            *(uint4*)&As[r * ASTR + c] = *(const uint4*)&A [(bm + r) * Kdim + k0 + c];
            *(uint4*)&Bs[r * ASTR + c] = *(const uint4*)&Bw[(bn + r) * Kdim + k0 + c];
        }
        __syncthreads();
#pragma unroll
        for (int kk = 0; kk < GK; kk += 16) {
            wmma::fragment<wmma::matrix_a, 16, 16, 16, __half, wmma::row_major> af[4];
            wmma::fragment<wmma::matrix_b, 16, 16, 16, __half, wmma::col_major> bf[2];
#pragma unroll
            for (int i = 0; i < 4; i++)
                wmma::load_matrix_sync(af[i], &As[(wr * 64 + i * 16) * ASTR + kk], ASTR);
#pragma unroll
            for (int j = 0; j < 2; j++)
                wmma::load_matrix_sync(bf[j], &Bs[(wc * 32 + j * 16) * ASTR + kk], ASTR);
#pragma unroll
            for (int i = 0; i < 4; i++)
#pragma unroll
                for (int j = 0; j < 2; j++)
                    wmma::mma_sync(acc[i][j], af[i], bf[j], acc[i][j]);
        }
        __syncthreads();
    }

#pragma unroll
    for (int i = 0; i < 4; i++)
#pragma unroll
        for (int j = 0; j < 2; j++) {
            float* cptr = &C[(bm + wr * 64 + i * 16) * Ndim + bn + wc * 32 + j * 16];
            if (ACCUM) {
                wmma::fragment<wmma::accumulator, 16, 16, 16, float> old;
                wmma::load_matrix_sync(old, cptr, Ndim, wmma::mem_row_major);
#pragma unroll
                for (int t = 0; t < old.num_elements; t++) acc[i][j].x[t] += old.x[t];
            }
            wmma::store_matrix_sync(cptr, acc[i][j], Ndim, wmma::mem_row_major);
        }
}

// ---------------- flash attention (causal optional via device scalar) ----------------
// Grid: (S/64, B*H). 128 threads (4 warps). Query tile 64 rows.
#define QSTR 136  // half stride for 128-wide tiles (128+8)
#define SSTR 68   // float stride for 64-wide scores
#define PSTR 72   // half stride for P
#define OSTR 132  // float stride for O/T

#define FLASH_SMEM (3 * 64 * QSTR * 2 /*Q,K,V*/ + 64 * SSTR * 4 /*Sc*/ + \
                    64 * PSTR * 2 /*P*/ + 2 * 64 * OSTR * 4 /*O,T*/ + (128 + 64 + 64) * 4)

__global__ __launch_bounds__(128, 1) void flash_kernel(
    const __half* __restrict__ Q, const __half* __restrict__ K,
    const __half* __restrict__ V, __half* __restrict__ Ch, __half* __restrict__ Cl,
    const int* __restrict__ um_ptr) {
    extern __shared__ char smem[];
    __half* Qs = (__half*)smem;            // 64 x QSTR
    __half* Ks = Qs + 64 * QSTR;
    __half* Vs = Ks + 64 * QSTR;
    float*  Sc = (float*)(Vs + 64 * QSTR); // 64 x SSTR
    __half* Ps = (__half*)(Sc + 64 * SSTR);
    float*  Os = (float*)(Ps + 64 * PSTR);
    float*  Ts = Os + 64 * OSTR;
    float*  red  = Ts + 64 * OSTR;         // 128
    float*  mrow = red + 128;              // 64
    float*  lrow = mrow + 64;              // 64

    const int tid  = threadIdx.x;
    const int warp = tid >> 5;
    const int qb = blockIdx.x;
    const int bh = blockIdx.y;
    const int um = *um_ptr;

    const __half* Qbase = Q + ((size_t)bh * Sv + qb * 64) * DKv;
#pragma unroll
    for (int t = 0; t < 8; t++) {
        int v = tid + t * 128;       // 0..1023
        int r = v >> 4, c = (v & 15) * 8;
        *(uint4*)&Qs[r * QSTR + c] = *(const uint4*)&Qbase[r * DKv + c];
    }
    for (int i = tid; i < 64 * OSTR; i += 128) Os[i] = 0.0f;
    if (tid < 64) { mrow[tid] = -1e30f; lrow[tid] = 0.0f; }
    __syncthreads();

    const int kb_end = um ? qb : (Sv / 64 - 1);
    const int row = tid >> 1, hf = tid & 1;
    const float scale = 0.08838834764831845f;  // 1/sqrt(128)

    for (int kb = 0; kb <= kb_end; ++kb) {
        const __half* Kbase = K + ((size_t)bh * Sv + kb * 64) * DKv;
        const __half* Vbase = V + ((size_t)bh * Sv + kb * 64) * DKv;
#pragma unroll
        for (int t = 0; t < 8; t++) {
            int v = tid + t * 128;
            int r = v >> 4, c = (v & 15) * 8;
            *(uint4*)&Ks[r * QSTR + c] = *(const uint4*)&Kbase[r * DKv + c];
            *(uint4*)&Vs[r * QSTR + c] = *(const uint4*)&Vbase[r * DKv + c];
        }
        __syncthreads();

        // S = Q * K^T  (each warp: 16 query rows x 64 keys)
        {
            wmma::fragment<wmma::accumulator, 16, 16, 16, float> sacc[4];
#pragma unroll
            for (int j = 0; j < 4; j++) wmma::fill_fragment(sacc[j], 0.0f);
#pragma unroll
            for (int kk = 0; kk < DKv; kk += 16) {
                wmma::fragment<wmma::matrix_a, 16, 16, 16, __half, wmma::row_major> qa;
                wmma::load_matrix_sync(qa, &Qs[(warp * 16) * QSTR + kk], QSTR);
#pragma unroll
                for (int j = 0; j < 4; j++) {
                    wmma::fragment<wmma::matrix_b, 16, 16, 16, __half, wmma::col_major> kf;
                    wmma::load_matrix_sync(kf, &Ks[(j * 16) * QSTR + kk], QSTR);
                    wmma::mma_sync(sacc[j], qa, kf, sacc[j]);
                }
            }
#pragma unroll
            for (int j = 0; j < 4; j++)
                wmma::store_matrix_sync(&Sc[(warp * 16) * SSTR + j * 16], sacc[j], SSTR,
                                        wmma::mem_row_major);
        }
        __syncthreads();

        // online softmax: 2 threads per row, 32 cols each
        {
            const int qg = qb * 64 + row;
            float vals[32];
            float lmax = -1e30f;
#pragma unroll
            for (int c = 0; c < 32; c++) {
                int kc = hf * 32 + c;
                float v = Sc[row * SSTR + kc] * scale;
                if (um && (kb * 64 + kc) > qg) v = -1e30f;
                vals[c] = v;
                lmax = fmaxf(lmax, v);
            }
            red[tid] = lmax;
            __syncthreads();
            float rmax = fmaxf(red[row * 2], red[row * 2 + 1]);
            float mo = mrow[row];
            float mn = fmaxf(mo, rmax);
            float alpha = __expf(mo - mn);
            float lsum = 0.0f;
#pragma unroll
            for (int c = 0; c < 32; c++) {
                float p = __expf(vals[c] - mn);
                lsum += p;
                Ps[row * PSTR + hf * 32 + c] = __float2half(p);
            }
            __syncthreads();              // reds consumed before overwrite
            red[tid] = lsum;
#pragma unroll
            for (int c = 0; c < 64; c++) Os[row * OSTR + hf * 64 + c] *= alpha;
            __syncthreads();
            if (hf == 0) {
                lrow[row] = lrow[row] * alpha + red[row * 2] + red[row * 2 + 1];
                mrow[row] = mn;
            }
            __syncthreads();
        }

        // T = P * V  (each warp: 16 rows x 128 cols)
        {
            wmma::fragment<wmma::accumulator, 16, 16, 16, float> oacc[8];
#pragma unroll
            for (int j = 0; j < 8; j++) wmma::fill_fragment(oacc[j], 0.0f);
#pragma unroll
            for (int kk = 0; kk < 64; kk += 16) {
                wmma::fragment<wmma::matrix_a, 16, 16, 16, __half, wmma::row_major> pa;
                wmma::load_matrix_sync(pa, &Ps[(warp * 16) * PSTR + kk], PSTR);
#pragma unroll
                for (int j = 0; j < 8; j++) {
                    wmma::fragment<wmma::matrix_b, 16, 16, 16, __half, wmma::row_major> vb;
                    wmma::load_matrix_sync(vb, &Vs[kk * QSTR + j * 16], QSTR);
                    wmma::mma_sync(oacc[j], pa, vb, oacc[j]);
                }
            }
#pragma unroll
            for (int j = 0; j < 8; j++)
                wmma::store_matrix_sync(&Ts[(warp * 16) * OSTR + j * 16], oacc[j], OSTR,
                                        wmma::mem_row_major);
        }
        __syncthreads();
        for (int i = tid; i < 64 * 128; i += 128) {
            int r = i >> 7, c = i & 127;
            Os[r * OSTR + c] += Ts[r * OSTR + c];
        }
        __syncthreads();
    }

    // epilogue: ctx hi/lo fp16 split, heads merged back to [B, S, H*DK]
    const int b = bh / Hv, h = bh % Hv;
    for (int i = tid; i < 64 * 128; i += 128) {
        int r = i >> 7, d = i & 127;
        float o = Os[r * OSTR + d] / lrow[r];
        __half hi = __float2half(o);
        __half lo = __float2half(o - __half2float(hi));
        size_t idx = (size_t)(b * Sv + qb * 64 + r) * DMv + h * DKv + d;
        Ch[idx] = hi;
        Cl[idx] = lo;
    }
}

// ---------------- launch ----------------
extern "C" void kernel_launch(void* const* d_in, const int* in_sizes, int n_in,
                              void* d_out, int out_size) {
    const float* x  = (const float*)d_in[0];
    const float* Wq = (const float*)d_in[1];
    const float* Wk = (const float*)d_in[2];
    const float* Wv = (const float*)d_in[3];
    const float* Wo = (const float*)d_in[4];
    const int*   um = (const int*)d_in[5];
    float* out = (float*)d_out;

    __half *Xh, *Wqh, *Wkh, *Wvh, *Woh, *Q, *K, *V, *Ch, *Cl;
    float* Y;
    cudaGetSymbolAddress((void**)&Xh,  g_Xh);
    cudaGetSymbolAddress((void**)&Wqh, g_Wqh);
    cudaGetSymbolAddress((void**)&Wkh, g_Wkh);
    cudaGetSymbolAddress((void**)&Wvh, g_Wvh);
    cudaGetSymbolAddress((void**)&Woh, g_Woh);
    cudaGetSymbolAddress((void**)&Y,   g_Y);
    cudaGetSymbolAddress((void**)&Q,   g_Q);
    cudaGetSymbolAddress((void**)&K,   g_K);
    cudaGetSymbolAddress((void**)&V,   g_V);
    cudaGetSymbolAddress((void**)&Ch,  g_Ch);
    cudaGetSymbolAddress((void**)&Cl,  g_Cl);

    f2h_kernel<<<8192, 256>>>(x,  Xh,  Mv * DMv);
    f2h_kernel<<<4096, 256>>>(Wq, Wqh, DMv * DMv);
    f2h_kernel<<<4096, 256>>>(Wk, Wkh, DMv * DMv);
    f2h_kernel<<<4096, 256>>>(Wv, Wvh, DMv * DMv);
    f2h_kernel<<<4096, 256>>>(Wo, Woh, DMv * DMv);

    dim3 gg(DMv / 128, Mv / 128);
    gemm_nt_kernel<false><<<gg, 256>>>(Xh, Wqh, Y, Mv, DMv, DMv);
    split_heads_kernel<<<8192, 256>>>(Y, Q);
    gemm_nt_kernel<false><<<gg, 256>>>(Xh, Wkh, Y, Mv, DMv, DMv);
    split_heads_kernel<<<8192, 256>>>(Y, K);
    gemm_nt_kernel<false><<<gg, 256>>>(Xh, Wvh, Y, Mv, DMv, DMv);
    split_heads_kernel<<<8192, 256>>>(Y, V);

    cudaFuncSetAttribute(flash_kernel, cudaFuncAttributeMaxDynamicSharedMemorySize,
                         FLASH_SMEM);
    flash_kernel<<<dim3(Sv / 64, Bv * Hv), 128, FLASH_SMEM>>>(Q, K, V, Ch, Cl, um);

    gemm_nt_kernel<false><<<gg, 256>>>(Ch, Woh, out, Mv, DMv, DMv);
    gemm_nt_kernel<true ><<<gg, 256>>>(Cl, Woh, out, Mv, DMv, DMv);
}

// round 3
// speedup vs baseline: 1.3377x; 1.3377x over previous
#include <cuda_runtime.h>
#include <cuda_fp16.h>
#include <mma.h>
#include <cstdint>

using namespace nvcuda;

// Problem constants
#define Bv 4
#define Sv 2048
#define Hv 16
#define DKv 128
#define DMv 2048
#define Mv (Bv * Sv)  // 8192

// ---------------- device scratch (static, allocation-free) ----------------
__device__ __half g_Xh [Mv * DMv];
__device__ __half g_Wqh[DMv * DMv];
__device__ __half g_Wkh[DMv * DMv];
__device__ __half g_Wvh[DMv * DMv];
__device__ __half g_Woh[DMv * DMv];
__device__ __half g_Q  [Mv * DMv];
__device__ __half g_K  [Mv * DMv];
__device__ __half g_V  [Mv * DMv];
__device__ __half g_Ch [Mv * DMv];
__device__ __half g_Cl [Mv * DMv];

// ---------------- cp.async helpers ----------------
__device__ __forceinline__ void cp16(void* s, const void* g) {
    unsigned int sa = (unsigned int)__cvta_generic_to_shared(s);
    asm volatile("cp.async.cg.shared.global [%0], [%1], 16;\n" :: "r"(sa), "l"(g));
}
__device__ __forceinline__ void cp_commit() { asm volatile("cp.async.commit_group;\n"); }
template <int N>
__device__ __forceinline__ void cp_wait() { asm volatile("cp.async.wait_group %0;\n" :: "n"(N)); }

// ---------------- fp32 -> fp16 convert (vector 8) ----------------
__global__ void f2h_kernel(const float4* __restrict__ in, uint4* __restrict__ out, int n8) {
    int i = blockIdx.x * blockDim.x + threadIdx.x;
    int stride = gridDim.x * blockDim.x;
    for (; i < n8; i += stride) {
        float4 a = in[i * 2], b = in[i * 2 + 1];
        __half2 h0 = __floats2half2_rn(a.x, a.y);
        __half2 h1 = __floats2half2_rn(a.z, a.w);
        __half2 h2 = __floats2half2_rn(b.x, b.y);
        __half2 h3 = __floats2half2_rn(b.z, b.w);
        uint4 o;
        o.x = *(unsigned int*)&h0; o.y = *(unsigned int*)&h1;
        o.z = *(unsigned int*)&h2; o.w = *(unsigned int*)&h3;
        out[i] = o;
    }
}

// ---------------- shared GEMM mainloop ----------------
// Block tile 128x128, BK=64, 2-stage cp.async double buffer.
// 8 warps: wr = warp>>2 (0..1) rows of 64, wc = warp&3 (0..3) cols of 32.
// C[M,N] = A[M,K] * B[N,K]^T
#define BK 64
#define KSTR 72                     // halves: 64 + 8 pad
#define BUFH (128 * KSTR)           // halves per tile buffer
#define GEMM_SMEM (2 * 2 * BUFH * 2)  // 73728 bytes

__device__ __forceinline__ void load_tiles(
    const __half* __restrict__ A, const __half* __restrict__ B, int Kdim,
    int bm, int bn, __half* As, __half* Bs, int buf, int k0, int tid) {
#pragma unroll
    for (int t = 0; t < 4; t++) {
        int v = tid + t * 256;          // 0..1023
        int r = v >> 3;                 // 0..127
        int c = (v & 7) * 8;            // 0..56
        cp16(&As[buf * BUFH + r * KSTR + c], &A[(size_t)(bm + r) * Kdim + k0 + c]);
        cp16(&Bs[buf * BUFH + r * KSTR + c], &B[(size_t)(bn + r) * Kdim + k0 + c]);
    }
    cp_commit();
}

__device__ __forceinline__ void gemm_mainloop(
    const __half* __restrict__ A, const __half* __restrict__ B, int Kdim,
    int bm, int bn, __half* As, __half* Bs,
    wmma::fragment<wmma::accumulator, 16, 16, 16, float> acc[4][2],
    int tid, int wr, int wc) {
    const int KT = Kdim / BK;
    load_tiles(A, B, Kdim, bm, bn, As, Bs, 0, 0, tid);
    for (int kt = 0; kt < KT; ++kt) {
        const int cur = kt & 1;
        if (kt + 1 < KT) {
            load_tiles(A, B, Kdim, bm, bn, As, Bs, cur ^ 1, (kt + 1) * BK, tid);
            cp_wait<1>();
        } else {
            cp_wait<0>();
        }
        __syncthreads();
        const __half* Ab = &As[cur * BUFH];
        const __half* Bb = &Bs[cur * BUFH];
#pragma unroll
        for (int kk = 0; kk < BK; kk += 16) {
            wmma::fragment<wmma::matrix_a, 16, 16, 16, __half, wmma::row_major> af[4];
            wmma::fragment<wmma::matrix_b, 16, 16, 16, __half, wmma::col_major> bf[2];
#pragma unroll
            for (int i = 0; i < 4; i++)
                wmma::load_matrix_sync(af[i], &Ab[(wr * 64 + i * 16) * KSTR + kk], KSTR);
#pragma unroll
            for (int j = 0; j < 2; j++)
                wmma::load_matrix_sync(bf[j], &Bb[(wc * 32 + j * 16) * KSTR + kk], KSTR);
#pragma unroll
            for (int i = 0; i < 4; i++)
#pragma unroll
                for (int j = 0; j < 2; j++)
                    wmma::mma_sync(acc[i][j], af[i], bf[j], acc[i][j]);
        }
        __syncthreads();
    }
}

// ---------------- fused QKV projection (direct split-head fp16 epilogue) ----------------
// grid (16, 64, 3): x = head (BN==DKv), y = row tile, z = which projection
__global__ __launch_bounds__(256) void gemm_qkv_kernel(
    const __half* __restrict__ X,
    const __half* __restrict__ Wq, const __half* __restrict__ Wk, const __half* __restrict__ Wv,
    __half* __restrict__ Q, __half* __restrict__ K, __half* __restrict__ V) {
    extern __shared__ char smem[];
    __half* As = (__half*)smem;
    __half* Bs = As + 2 * BUFH;

    const __half* Bw = (blockIdx.z == 0) ? Wq : (blockIdx.z == 1) ? Wk : Wv;
    __half* O = (blockIdx.z == 0) ? Q : (blockIdx.z == 1) ? K : V;

    const int tid = threadIdx.x, warp = tid >> 5;
    const int wr = warp >> 2, wc = warp & 3;
    const int bm = blockIdx.y * 128, bn = blockIdx.x * 128;

    wmma::fragment<wmma::accumulator, 16, 16, 16, float> acc[4][2];
#pragma unroll
    for (int i = 0; i < 4; i++)
#pragma unroll
        for (int j = 0; j < 2; j++) wmma::fill_fragment(acc[i][j], 0.0f);

    gemm_mainloop(X, Bw, DMv, bm, bn, As, Bs, acc, tid, wr, wc);

    // epilogue: stage f32 in smem, convert to fp16 split-head layout
    float* Cs = (float*)smem;  // 128 x 132
    __syncthreads();
#pragma unroll
    for (int i = 0; i < 4; i++)
#pragma unroll
        for (int j = 0; j < 2; j++)
            wmma::store_matrix_sync(&Cs[(wr * 64 + i * 16) * 132 + wc * 32 + j * 16],
                                    acc[i][j], 132, wmma::mem_row_major);
    __syncthreads();

    const int b = bm >> 11, s0 = bm & (Sv - 1), h = blockIdx.x;
    __half* Ob = O + (((size_t)(b * Hv + h)) * Sv + s0) * DKv;
    for (int i = tid; i < 128 * 128; i += 256) {
        int r = i >> 7, d = i & 127;
        Ob[r * DKv + d] = __float2half(Cs[r * 132 + d]);
    }
}

// ---------------- output projection GEMM (f32 out, optional accumulate) ----------------
template <bool ACCUM>
__global__ __launch_bounds__(256) void gemm_out_kernel(
    const __half* __restrict__ A, const __half* __restrict__ Bw, float* __restrict__ C) {
    extern __shared__ char smem[];
    __half* As = (__half*)smem;
    __half* Bs = As + 2 * BUFH;

    const int tid = threadIdx.x, warp = tid >> 5;
    const int wr = warp >> 2, wc = warp & 3;
    const int bm = blockIdx.y * 128, bn = blockIdx.x * 128;

    wmma::fragment<wmma::accumulator, 16, 16, 16, float> acc[4][2];
#pragma unroll
    for (int i = 0; i < 4; i++)
#pragma unroll
        for (int j = 0; j < 2; j++) wmma::fill_fragment(acc[i][j], 0.0f);

    gemm_mainloop(A, Bw, DMv, bm, bn, As, Bs, acc, tid, wr, wc);

#pragma unroll
    for (int i = 0; i < 4; i++)
#pragma unroll
        for (int j = 0; j < 2; j++) {
            float* cptr = &C[(size_t)(bm + wr * 64 + i * 16) * DMv + bn + wc * 32 + j * 16];
            if (ACCUM) {
                wmma::fragment<wmma::accumulator, 16, 16, 16, float> old;
                wmma::load_matrix_sync(old, cptr, DMv, wmma::mem_row_major);
#pragma unroll
                for (int t = 0; t < old.num_elements; t++) acc[i][j].x[t] += old.x[t];
            }
            wmma::store_matrix_sync(cptr, acc[i][j], DMv, wmma::mem_row_major);
        }
}

// ---------------- flash attention (causal optional via device scalar) ----------------
#define QSTR 136
#define SSTR 68
#define PSTR 72
#define OSTR 132

#define FLASH_SMEM (3 * 64 * QSTR * 2 + 64 * SSTR * 4 + \
                    64 * PSTR * 2 + 2 * 64 * OSTR * 4 + (128 + 64 + 64) * 4)

__global__ __launch_bounds__(128, 1) void flash_kernel(
    const __half* __restrict__ Q, const __half* __restrict__ K,
    const __half* __restrict__ V, __half* __restrict__ Ch, __half* __restrict__ Cl,
    const int* __restrict__ um_ptr) {
    extern __shared__ char smem[];
    __half* Qs = (__half*)smem;
    __half* Ks = Qs + 64 * QSTR;
    __half* Vs = Ks + 64 * QSTR;
    float*  Sc = (float*)(Vs + 64 * QSTR);
    __half* Ps = (__half*)(Sc + 64 * SSTR);
    float*  Os = (float*)(Ps + 64 * PSTR);
    float*  Ts = Os + 64 * OSTR;
    float*  red  = Ts + 64 * OSTR;
    float*  mrow = red + 128;
    float*  lrow = mrow + 64;

    const int tid  = threadIdx.x;
    const int warp = tid >> 5;
    const int qb = blockIdx.x;
    const int bh = blockIdx.y;
    const int um = *um_ptr;

    const __half* Qbase = Q + ((size_t)bh * Sv + qb * 64) * DKv;
#pragma unroll
    for (int t = 0; t < 8; t++) {
        int v = tid + t * 128;
        int r = v >> 4, c = (v & 15) * 8;
        *(uint4*)&Qs[r * QSTR + c] = *(const uint4*)&Qbase[r * DKv + c];
    }
    for (int i = tid; i < 64 * OSTR; i += 128) Os[i] = 0.0f;
    if (tid < 64) { mrow[tid] = -1e30f; lrow[tid] = 0.0f; }
    __syncthreads();

    const int kb_end = um ? qb : (Sv / 64 - 1);
    const int row = tid >> 1, hf = tid & 1;
    const float scale = 0.08838834764831845f;

    for (int kb = 0; kb <= kb_end; ++kb) {
        const __half* Kbase = K + ((size_t)bh * Sv + kb * 64) * DKv;
        const __half* Vbase = V + ((size_t)bh * Sv + kb * 64) * DKv;
#pragma unroll
        for (int t = 0; t < 8; t++) {
            int v = tid + t * 128;
            int r = v >> 4, c = (v & 15) * 8;
            *(uint4*)&Ks[r * QSTR + c] = *(const uint4*)&Kbase[r * DKv + c];
            *(uint4*)&Vs[r * QSTR + c] = *(const uint4*)&Vbase[r * DKv + c];
        }
        __syncthreads();

        {
            wmma::fragment<wmma::accumulator, 16, 16, 16, float> sacc[4];
#pragma unroll
            for (int j = 0; j < 4; j++) wmma::fill_fragment(sacc[j], 0.0f);
#pragma unroll
            for (int kk = 0; kk < DKv; kk += 16) {
                wmma::fragment<wmma::matrix_a, 16, 16, 16, __half, wmma::row_major> qa;
                wmma::load_matrix_sync(qa, &Qs[(warp * 16) * QSTR + kk], QSTR);
#pragma unroll
                for (int j = 0; j < 4; j++) {
                    wmma::fragment<wmma::matrix_b, 16, 16, 16, __half, wmma::col_major> kf;
                    wmma::load_matrix_sync(kf, &Ks[(j * 16) * QSTR + kk], QSTR);
                    wmma::mma_sync(sacc[j], qa, kf, sacc[j]);
                }
            }
#pragma unroll
            for (int j = 0; j < 4; j++)
                wmma::store_matrix_sync(&Sc[(warp * 16) * SSTR + j * 16], sacc[j], SSTR,
                                        wmma::mem_row_major);
        }
        __syncthreads();

        {
            const int qg = qb * 64 + row;
            float vals[32];
            float lmax = -1e30f;
#pragma unroll
            for (int c = 0; c < 32; c++) {
                int kc = hf * 32 + c;
                float v = Sc[row * SSTR + kc] * scale;
                if (um && (kb * 64 + kc) > qg) v = -1e30f;
                vals[c] = v;
                lmax = fmaxf(lmax, v);
            }
            red[tid] = lmax;
            __syncthreads();
            float rmax = fmaxf(red[row * 2], red[row * 2 + 1]);
            float mo = mrow[row];
            float mn = fmaxf(mo, rmax);
            float alpha = __expf(mo - mn);
            float lsum = 0.0f;
#pragma unroll
            for (int c = 0; c < 32; c++) {
                float p = __expf(vals[c] - mn);
                lsum += p;
                Ps[row * PSTR + hf * 32 + c] = __float2half(p);
            }
            __syncthreads();
            red[tid] = lsum;
#pragma unroll
            for (int c = 0; c < 64; c++) Os[row * OSTR + hf * 64 + c] *= alpha;
            __syncthreads();
            if (hf == 0) {
                lrow[row] = lrow[row] * alpha + red[row * 2] + red[row * 2 + 1];
                mrow[row] = mn;
            }
            __syncthreads();
        }

        {
            wmma::fragment<wmma::accumulator, 16, 16, 16, float> oacc[8];
#pragma unroll
            for (int j = 0; j < 8; j++) wmma::fill_fragment(oacc[j], 0.0f);
#pragma unroll
            for (int kk = 0; kk < 64; kk += 16) {
                wmma::fragment<wmma::matrix_a, 16, 16, 16, __half, wmma::row_major> pa;
                wmma::load_matrix_sync(pa, &Ps[(warp * 16) * PSTR + kk], PSTR);
#pragma unroll
                for (int j = 0; j < 8; j++) {
                    wmma::fragment<wmma::matrix_b, 16, 16, 16, __half, wmma::row_major> vb;
                    wmma::load_matrix_sync(vb, &Vs[kk * QSTR + j * 16], QSTR);
                    wmma::mma_sync(oacc[j], pa, vb, oacc[j]);
                }
            }
#pragma unroll
            for (int j = 0; j < 8; j++)
                wmma::store_matrix_sync(&Ts[(warp * 16) * OSTR + j * 16], oacc[j], OSTR,
                                        wmma::mem_row_major);
        }
        __syncthreads();
        for (int i = tid; i < 64 * 128; i += 128) {
            int r = i >> 7, c = i & 127;
            Os[r * OSTR + c] += Ts[r * OSTR + c];
        }
        __syncthreads();
    }

    const int b = bh / Hv, h = bh % Hv;
    for (int i = tid; i < 64 * 128; i += 128) {
        int r = i >> 7, d = i & 127;
        float o = Os[r * OSTR + d] / lrow[r];
        __half hi = __float2half(o);
        __half lo = __float2half(o - __half2float(hi));
        size_t idx = (size_t)(b * Sv + qb * 64 + r) * DMv + h * DKv + d;
        Ch[idx] = hi;
        Cl[idx] = lo;
    }
}

// ---------------- launch ----------------
extern "C" void kernel_launch(void* const* d_in, const int* in_sizes, int n_in,
                              void* d_out, int out_size) {
    const float* x  = (const float*)d_in[0];
    const float* Wq = (const float*)d_in[1];
    const float* Wk = (const float*)d_in[2];
    const float* Wv = (const float*)d_in[3];
    const float* Wo = (const float*)d_in[4];
    const int*   um = (const int*)d_in[5];
    float* out = (float*)d_out;

    __half *Xh, *Wqh, *Wkh, *Wvh, *Woh, *Q, *K, *V, *Ch, *Cl;
    cudaGetSymbolAddress((void**)&Xh,  g_Xh);
    cudaGetSymbolAddress((void**)&Wqh, g_Wqh);
    cudaGetSymbolAddress((void**)&Wkh, g_Wkh);
    cudaGetSymbolAddress((void**)&Wvh, g_Wvh);
    cudaGetSymbolAddress((void**)&Woh, g_Woh);
    cudaGetSymbolAddress((void**)&Q,   g_Q);
    cudaGetSymbolAddress((void**)&K,   g_K);
    cudaGetSymbolAddress((void**)&V,   g_V);
    cudaGetSymbolAddress((void**)&Ch,  g_Ch);
    cudaGetSymbolAddress((void**)&Cl,  g_Cl);

    f2h_kernel<<<2048, 256>>>((const float4*)x,  (uint4*)Xh,  Mv * DMv / 8);
    f2h_kernel<<<1024, 256>>>((const float4*)Wq, (uint4*)Wqh, DMv * DMv / 8);
    f2h_kernel<<<1024, 256>>>((const float4*)Wk, (uint4*)Wkh, DMv * DMv / 8);
    f2h_kernel<<<1024, 256>>>((const float4*)Wv, (uint4*)Wvh, DMv * DMv / 8);
    f2h_kernel<<<1024, 256>>>((const float4*)Wo, (uint4*)Woh, DMv * DMv / 8);

    cudaFuncSetAttribute(gemm_qkv_kernel, cudaFuncAttributeMaxDynamicSharedMemorySize, GEMM_SMEM);
    cudaFuncSetAttribute(gemm_out_kernel<false>, cudaFuncAttributeMaxDynamicSharedMemorySize, GEMM_SMEM);
    cudaFuncSetAttribute(gemm_out_kernel<true>,  cudaFuncAttributeMaxDynamicSharedMemorySize, GEMM_SMEM);
    cudaFuncSetAttribute(flash_kernel, cudaFuncAttributeMaxDynamicSharedMemorySize, FLASH_SMEM);

    gemm_qkv_kernel<<<dim3(16, 64, 3), 256, GEMM_SMEM>>>(Xh, Wqh, Wkh, Wvh, Q, K, V);

    flash_kernel<<<dim3(Sv / 64, Bv * Hv), 128, FLASH_SMEM>>>(Q, K, V, Ch, Cl, um);

    dim3 gg(16, 64);
    gemm_out_kernel<false><<<gg, 256, GEMM_SMEM>>>(Ch, Woh, out);
    gemm_out_kernel<true ><<<gg, 256, GEMM_SMEM>>>(Cl, Woh, out);
}

// round 4
// speedup vs baseline: 1.6514x; 1.2345x over previous
#include <cuda_runtime.h>
#include <cuda_fp16.h>
#include <mma.h>
#include <cstdint>

using namespace nvcuda;

// Problem constants
#define Bv 4
#define Sv 2048
#define Hv 16
#define DKv 128
#define DMv 2048
#define Mv (Bv * Sv)  // 8192

// ---------------- device scratch (static, allocation-free) ----------------
__device__ __half g_Xh [Mv * DMv];
__device__ __half g_Wqh[DMv * DMv];
__device__ __half g_Wkh[DMv * DMv];
__device__ __half g_Wvh[DMv * DMv];
__device__ __half g_Woh[DMv * DMv];
__device__ __half g_Q  [Mv * DMv];
__device__ __half g_K  [Mv * DMv];
__device__ __half g_V  [Mv * DMv];
__device__ __half g_Ch [Mv * DMv];

// ---------------- cp.async helpers ----------------
__device__ __forceinline__ void cp16(void* s, const void* g) {
    unsigned int sa = (unsigned int)__cvta_generic_to_shared(s);
    asm volatile("cp.async.cg.shared.global [%0], [%1], 16;\n" :: "r"(sa), "l"(g));
}
__device__ __forceinline__ void cp_commit() { asm volatile("cp.async.commit_group;\n"); }
template <int N>
__device__ __forceinline__ void cp_wait() { asm volatile("cp.async.wait_group %0;\n" :: "n"(N)); }

// ---------------- fp32 -> fp16 convert (vector 8) ----------------
__global__ void f2h_kernel(const float4* __restrict__ in, uint4* __restrict__ out, int n8) {
    int i = blockIdx.x * blockDim.x + threadIdx.x;
    int stride = gridDim.x * blockDim.x;
    for (; i < n8; i += stride) {
        float4 a = in[i * 2], b = in[i * 2 + 1];
        __half2 h0 = __floats2half2_rn(a.x, a.y);
        __half2 h1 = __floats2half2_rn(a.z, a.w);
        __half2 h2 = __floats2half2_rn(b.x, b.y);
        __half2 h3 = __floats2half2_rn(b.z, b.w);
        uint4 o;
        o.x = *(unsigned int*)&h0; o.y = *(unsigned int*)&h1;
        o.z = *(unsigned int*)&h2; o.w = *(unsigned int*)&h3;
        out[i] = o;
    }
}

// ---------------- shared GEMM mainloop ----------------
// Block tile 128x128, BK=64, 3-stage cp.async ring, ONE syncthreads per k-tile.
// 8 warps: wr = warp>>2 (0..1) rows of 64, wc = warp&3 (0..3) cols of 32.
// C[M,N] = A[M,K] * B[N,K]^T
#define BK 64
#define KSTR 72                     // halves: 64 + 8 pad
#define BUFH (128 * KSTR)           // halves per tile buffer
#define NSTG 3
#define GEMM_SMEM (NSTG * 2 * BUFH * 2)  // 110592 bytes

__device__ __forceinline__ void load_tiles(
    const __half* __restrict__ A, const __half* __restrict__ B, int Kdim,
    int bm, int bn, __half* As, __half* Bs, int stg, int k0, int tid) {
#pragma unroll
    for (int t = 0; t < 4; t++) {
        int v = tid + t * 256;          // 0..1023
        int r = v >> 3;                 // 0..127
        int c = (v & 7) * 8;            // 0..56
        cp16(&As[stg * BUFH + r * KSTR + c], &A[(size_t)(bm + r) * Kdim + k0 + c]);
        cp16(&Bs[stg * BUFH + r * KSTR + c], &B[(size_t)(bn + r) * Kdim + k0 + c]);
    }
    cp_commit();
}

__device__ __forceinline__ void gemm_mainloop(
    const __half* __restrict__ A, const __half* __restrict__ B, int Kdim,
    int bm, int bn, __half* As, __half* Bs,
    wmma::fragment<wmma::accumulator, 16, 16, 16, float> acc[4][2],
    int tid, int wr, int wc) {
    const int KT = Kdim / BK;
    load_tiles(A, B, Kdim, bm, bn, As, Bs, 0, 0, tid);
    load_tiles(A, B, Kdim, bm, bn, As, Bs, 1, BK, tid);
    int stg = 0;
    for (int kt = 0; kt < KT; ++kt) {
        cp_wait<1>();
        __syncthreads();
        const __half* Ab = &As[stg * BUFH];
        const __half* Bb = &Bs[stg * BUFH];
#pragma unroll
        for (int kk = 0; kk < BK; kk += 16) {
            wmma::fragment<wmma::matrix_a, 16, 16, 16, __half, wmma::row_major> af[4];
            wmma::fragment<wmma::matrix_b, 16, 16, 16, __half, wmma::col_major> bf[2];
#pragma unroll
            for (int i = 0; i < 4; i++)
                wmma::load_matrix_sync(af[i], &Ab[(wr * 64 + i * 16) * KSTR + kk], KSTR);
#pragma unroll
            for (int j = 0; j < 2; j++)
                wmma::load_matrix_sync(bf[j], &Bb[(wc * 32 + j * 16) * KSTR + kk], KSTR);
#pragma unroll
            for (int i = 0; i < 4; i++)
#pragma unroll
                for (int j = 0; j < 2; j++)
                    wmma::mma_sync(acc[i][j], af[i], bf[j], acc[i][j]);
        }
        if (kt + 2 < KT) {
            int ns = stg + 2; if (ns >= NSTG) ns -= NSTG;
            load_tiles(A, B, Kdim, bm, bn, As, Bs, ns, (kt + 2) * BK, tid);
        } else {
            cp_commit();  // keep group count in step for cp_wait<1>
        }
        if (++stg == NSTG) stg = 0;
    }
}

// ---------------- fused QKV projection (direct split-head fp16 epilogue) ----------------
// grid (16, 64, 3): x = head (BN==DKv), y = row tile, z = which projection
__global__ __launch_bounds__(256) void gemm_qkv_kernel(
    const __half* __restrict__ X,
    const __half* __restrict__ Wq, const __half* __restrict__ Wk, const __half* __restrict__ Wv,
    __half* __restrict__ Q, __half* __restrict__ K, __half* __restrict__ V) {
    extern __shared__ char smem[];
    __half* As = (__half*)smem;
    __half* Bs = As + NSTG * BUFH;

    const __half* Bw = (blockIdx.z == 0) ? Wq : (blockIdx.z == 1) ? Wk : Wv;
    __half* O = (blockIdx.z == 0) ? Q : (blockIdx.z == 1) ? K : V;

    const int tid = threadIdx.x, warp = tid >> 5;
    const int wr = warp >> 2, wc = warp & 3;
    const int bm = blockIdx.y * 128, bn = blockIdx.x * 128;

    wmma::fragment<wmma::accumulator, 16, 16, 16, float> acc[4][2];
#pragma unroll
    for (int i = 0; i < 4; i++)
#pragma unroll
        for (int j = 0; j < 2; j++) wmma::fill_fragment(acc[i][j], 0.0f);

    gemm_mainloop(X, Bw, DMv, bm, bn, As, Bs, acc, tid, wr, wc);

    // epilogue: stage f32 in smem, convert to fp16 split-head layout
    float* Cs = (float*)smem;  // 128 x 132
    __syncthreads();
#pragma unroll
    for (int i = 0; i < 4; i++)
#pragma unroll
        for (int j = 0; j < 2; j++)
            wmma::store_matrix_sync(&Cs[(wr * 64 + i * 16) * 132 + wc * 32 + j * 16],
                                    acc[i][j], 132, wmma::mem_row_major);
    __syncthreads();

    const int b = bm >> 11, s0 = bm & (Sv - 1), h = blockIdx.x;
    __half* Ob = O + (((size_t)(b * Hv + h)) * Sv + s0) * DKv;
    for (int i = tid; i < 128 * 128; i += 256) {
        int r = i >> 7, d = i & 127;
        Ob[r * DKv + d] = __float2half(Cs[r * 132 + d]);
    }
}

// ---------------- output projection GEMM (f32 out) ----------------
__global__ __launch_bounds__(256) void gemm_out_kernel(
    const __half* __restrict__ A, const __half* __restrict__ Bw, float* __restrict__ C) {
    extern __shared__ char smem[];
    __half* As = (__half*)smem;
    __half* Bs = As + NSTG * BUFH;

    const int tid = threadIdx.x, warp = tid >> 5;
    const int wr = warp >> 2, wc = warp & 3;
    const int bm = blockIdx.y * 128, bn = blockIdx.x * 128;

    wmma::fragment<wmma::accumulator, 16, 16, 16, float> acc[4][2];
#pragma unroll
    for (int i = 0; i < 4; i++)
#pragma unroll
        for (int j = 0; j < 2; j++) wmma::fill_fragment(acc[i][j], 0.0f);

    gemm_mainloop(A, Bw, DMv, bm, bn, As, Bs, acc, tid, wr, wc);

#pragma unroll
    for (int i = 0; i < 4; i++)
#pragma unroll
        for (int j = 0; j < 2; j++) {
            float* cptr = &C[(size_t)(bm + wr * 64 + i * 16) * DMv + bn + wc * 32 + j * 16];
            wmma::store_matrix_sync(cptr, acc[i][j], DMv, wmma::mem_row_major);
        }
}

// ---------------- flash attention (causal optional via device scalar) ----------------
#define QSTR 136
#define SSTR 68
#define PSTR 72
#define OSTR 132

#define FLASH_SMEM (3 * 64 * QSTR * 2 + 64 * SSTR * 4 + \
                    64 * PSTR * 2 + 2 * 64 * OSTR * 4 + (128 + 64 + 64 + 64) * 4)

__global__ __launch_bounds__(128, 1) void flash_kernel(
    const __half* __restrict__ Q, const __half* __restrict__ K,
    const __half* __restrict__ V, __half* __restrict__ Ch,
    const int* __restrict__ um_ptr) {
    extern __shared__ char smem[];
    __half* Qs = (__half*)smem;
    __half* Ks = Qs + 64 * QSTR;
    __half* Vs = Ks + 64 * QSTR;
    float*  Sc = (float*)(Vs + 64 * QSTR);
    __half* Ps = (__half*)(Sc + 64 * SSTR);
    float*  Os = (float*)(Ps + 64 * PSTR);
    float*  Ts = Os + 64 * OSTR;
    float*  red  = Ts + 64 * OSTR;     // 128
    float*  mrow = red + 128;          // 64
    float*  lrow = mrow + 64;          // 64
    float*  arow = lrow + 64;          // 64

    const int tid  = threadIdx.x;
    const int warp = tid >> 5;
    const int qb = blockIdx.x;
    const int bh = blockIdx.y;
    const int um = *um_ptr;

    const __half* Qbase = Q + ((size_t)bh * Sv + qb * 64) * DKv;
#pragma unroll
    for (int t = 0; t < 8; t++) {
        int v = tid + t * 128;
        int r = v >> 4, c = (v & 15) * 8;
        *(uint4*)&Qs[r * QSTR + c] = *(const uint4*)&Qbase[r * DKv + c];
    }
    for (int i = tid; i < 64 * OSTR; i += 128) Os[i] = 0.0f;
    if (tid < 64) { mrow[tid] = -1e30f; lrow[tid] = 0.0f; }
    __syncthreads();

    const int kb_end = um ? qb : (Sv / 64 - 1);
    const int row = tid >> 1, hf = tid & 1;
    const float scale = 0.08838834764831845f;

    for (int kb = 0; kb <= kb_end; ++kb) {
        const __half* Kbase = K + ((size_t)bh * Sv + kb * 64) * DKv;
        const __half* Vbase = V + ((size_t)bh * Sv + kb * 64) * DKv;
#pragma unroll
        for (int t = 0; t < 8; t++) {
            int v = tid + t * 128;
            int r = v >> 4, c = (v & 15) * 8;
            *(uint4*)&Ks[r * QSTR + c] = *(const uint4*)&Kbase[r * DKv + c];
            *(uint4*)&Vs[r * QSTR + c] = *(const uint4*)&Vbase[r * DKv + c];
        }
        __syncthreads();

        // S = Q * K^T
        {
            wmma::fragment<wmma::accumulator, 16, 16, 16, float> sacc[4];
#pragma unroll
            for (int j = 0; j < 4; j++) wmma::fill_fragment(sacc[j], 0.0f);
#pragma unroll
            for (int kk = 0; kk < DKv; kk += 16) {
                wmma::fragment<wmma::matrix_a, 16, 16, 16, __half, wmma::row_major> qa;
                wmma::load_matrix_sync(qa, &Qs[(warp * 16) * QSTR + kk], QSTR);
#pragma unroll
                for (int j = 0; j < 4; j++) {
                    wmma::fragment<wmma::matrix_b, 16, 16, 16, __half, wmma::col_major> kf;
                    wmma::load_matrix_sync(kf, &Ks[(j * 16) * QSTR + kk], QSTR);
                    wmma::mma_sync(sacc[j], qa, kf, sacc[j]);
                }
            }
#pragma unroll
            for (int j = 0; j < 4; j++)
                wmma::store_matrix_sync(&Sc[(warp * 16) * SSTR + j * 16], sacc[j], SSTR,
                                        wmma::mem_row_major);
        }
        __syncthreads();

        // online softmax: 2 threads per row, 32 cols each
        {
            const int qg = qb * 64 + row;
            float vals[32];
            float lmax = -1e30f;
#pragma unroll
            for (int c = 0; c < 32; c++) {
                int kc = hf * 32 + c;
                float v = Sc[row * SSTR + kc] * scale;
                if (um && (kb * 64 + kc) > qg) v = -1e30f;
                vals[c] = v;
                lmax = fmaxf(lmax, v);
            }
            red[tid] = lmax;
            __syncthreads();
            float rmax = fmaxf(red[row * 2], red[row * 2 + 1]);
            float mo = mrow[row];
            float mn = fmaxf(mo, rmax);
            float alpha = __expf(mo - mn);
            float lsum = 0.0f;
#pragma unroll
            for (int c = 0; c < 32; c++) {
                float p = __expf(vals[c] - mn);
                lsum += p;
                Ps[row * PSTR + hf * 32 + c] = __float2half(p);
            }
            __syncthreads();              // red reads done; Ps visible
            red[tid] = lsum;
            if (hf == 0) { arow[row] = alpha; mrow[row] = mn; }
            __syncthreads();
            if (hf == 0)
                lrow[row] = lrow[row] * alpha + red[row * 2] + red[row * 2 + 1];
        }

        // T = P * V
        {
            wmma::fragment<wmma::accumulator, 16, 16, 16, float> oacc[8];
#pragma unroll
            for (int j = 0; j < 8; j++) wmma::fill_fragment(oacc[j], 0.0f);
#pragma unroll
            for (int kk = 0; kk < 64; kk += 16) {
                wmma::fragment<wmma::matrix_a, 16, 16, 16, __half, wmma::row_major> pa;
                wmma::load_matrix_sync(pa, &Ps[(warp * 16) * PSTR + kk], PSTR);
#pragma unroll
                for (int j = 0; j < 8; j++) {
                    wmma::fragment<wmma::matrix_b, 16, 16, 16, __half, wmma::row_major> vb;
                    wmma::load_matrix_sync(vb, &Vs[kk * QSTR + j * 16], QSTR);
                    wmma::mma_sync(oacc[j], pa, vb, oacc[j]);
                }
            }
#pragma unroll
            for (int j = 0; j < 8; j++)
                wmma::store_matrix_sync(&Ts[(warp * 16) * OSTR + j * 16], oacc[j], OSTR,
                                        wmma::mem_row_major);
        }
        __syncthreads();
        // fused rescale + accumulate
        for (int i = tid; i < 64 * 128; i += 128) {
            int r = i >> 7, c = i & 127;
            Os[r * OSTR + c] = Os[r * OSTR + c] * arow[r] + Ts[r * OSTR + c];
        }
        __syncthreads();
    }

    // epilogue: ctx fp16, heads merged back to [B, S, H*DK]
    const int b = bh / Hv, h = bh % Hv;
    for (int i = tid; i < 64 * 128; i += 128) {
        int r = i >> 7, d = i & 127;
        float o = Os[r * OSTR + d] / lrow[r];
        size_t idx = (size_t)(b * Sv + qb * 64 + r) * DMv + h * DKv + d;
        Ch[idx] = __float2half(o);
    }
}

// ---------------- launch ----------------
extern "C" void kernel_launch(void* const* d_in, const int* in_sizes, int n_in,
                              void* d_out, int out_size) {
    const float* x  = (const float*)d_in[0];
    const float* Wq = (const float*)d_in[1];
    const float* Wk = (const float*)d_in[2];
    const float* Wv = (const float*)d_in[3];
    const float* Wo = (const float*)d_in[4];
    const int*   um = (const int*)d_in[5];
    float* out = (float*)d_out;

    __half *Xh, *Wqh, *Wkh, *Wvh, *Woh, *Q, *K, *V, *Ch;
    cudaGetSymbolAddress((void**)&Xh,  g_Xh);
    cudaGetSymbolAddress((void**)&Wqh, g_Wqh);
    cudaGetSymbolAddress((void**)&Wkh, g_Wkh);
    cudaGetSymbolAddress((void**)&Wvh, g_Wvh);
    cudaGetSymbolAddress((void**)&Woh, g_Woh);
    cudaGetSymbolAddress((void**)&Q,   g_Q);
    cudaGetSymbolAddress((void**)&K,   g_K);
    cudaGetSymbolAddress((void**)&V,   g_V);
    cudaGetSymbolAddress((void**)&Ch,  g_Ch);

    f2h_kernel<<<2048, 256>>>((const float4*)x,  (uint4*)Xh,  Mv * DMv / 8);
    f2h_kernel<<<1024, 256>>>((const float4*)Wq, (uint4*)Wqh, DMv * DMv / 8);
    f2h_kernel<<<1024, 256>>>((const float4*)Wk, (uint4*)Wkh, DMv * DMv / 8);
    f2h_kernel<<<1024, 256>>>((const float4*)Wv, (uint4*)Wvh, DMv * DMv / 8);
    f2h_kernel<<<1024, 256>>>((const float4*)Wo, (uint4*)Woh, DMv * DMv / 8);

    cudaFuncSetAttribute(gemm_qkv_kernel, cudaFuncAttributeMaxDynamicSharedMemorySize, GEMM_SMEM);
    cudaFuncSetAttribute(gemm_out_kernel, cudaFuncAttributeMaxDynamicSharedMemorySize, GEMM_SMEM);
    cudaFuncSetAttribute(flash_kernel, cudaFuncAttributeMaxDynamicSharedMemorySize, FLASH_SMEM);

    gemm_qkv_kernel<<<dim3(16, 64, 3), 256, GEMM_SMEM>>>(Xh, Wqh, Wkh, Wvh, Q, K, V);

    flash_kernel<<<dim3(Sv / 64, Bv * Hv), 128, FLASH_SMEM>>>(Q, K, V, Ch, um);

    gemm_out_kernel<<<dim3(16, 64), 256, GEMM_SMEM>>>(Ch, Woh, out);
}

// round 8
// speedup vs baseline: 2.2158x; 1.3418x over previous
#include <cuda_runtime.h>
#include <cuda_fp16.h>
#include <mma.h>
#include <cstdint>

using namespace nvcuda;

// Problem constants
#define Bv 4
#define Sv 2048
#define Hv 16
#define DKv 128
#define DMv 2048
#define Mv (Bv * Sv)  // 8192

// ---------------- device scratch (static, allocation-free) ----------------
__device__ __half g_Xh [Mv * DMv];
__device__ __half g_Wqh[DMv * DMv];
__device__ __half g_Wkh[DMv * DMv];
__device__ __half g_Wvh[DMv * DMv];
__device__ __half g_Woh[DMv * DMv];
__device__ __half g_Q  [Mv * DMv];
__device__ __half g_K  [Mv * DMv];
__device__ __half g_V  [Mv * DMv];
__device__ __half g_Ch [Mv * DMv];

// ---------------- cp.async helpers ----------------
__device__ __forceinline__ void cp16(void* s, const void* g) {
    unsigned int sa = (unsigned int)__cvta_generic_to_shared(s);
    asm volatile("cp.async.cg.shared.global [%0], [%1], 16;\n" :: "r"(sa), "l"(g));
}
__device__ __forceinline__ void cp_commit() { asm volatile("cp.async.commit_group;\n"); }
template <int N>
__device__ __forceinline__ void cp_wait() { asm volatile("cp.async.wait_group %0;\n" :: "n"(N)); }

// ---------------- fp32 -> fp16 convert (vector 8) ----------------
__global__ void f2h_kernel(const float4* __restrict__ in, uint4* __restrict__ out, int n8) {
    int i = blockIdx.x * blockDim.x + threadIdx.x;
    int stride = gridDim.x * blockDim.x;
    for (; i < n8; i += stride) {
        float4 a = in[i * 2], b = in[i * 2 + 1];
        __half2 h0 = __floats2half2_rn(a.x, a.y);
        __half2 h1 = __floats2half2_rn(a.z, a.w);
        __half2 h2 = __floats2half2_rn(b.x, b.y);
        __half2 h3 = __floats2half2_rn(b.z, b.w);
        uint4 o;
        o.x = *(unsigned int*)&h0; o.y = *(unsigned int*)&h1;
        o.z = *(unsigned int*)&h2; o.w = *(unsigned int*)&h3;
        out[i] = o;
    }
}

// ---------------- shared GEMM mainloop ----------------
// Block tile 128x128, BK=64, 3-stage cp.async ring, ONE syncthreads per k-tile.
#define BK 64
#define KSTR 72
#define BUFH (128 * KSTR)
#define NSTG 3
#define GEMM_SMEM (NSTG * 2 * BUFH * 2)  // 110592 bytes

__device__ __forceinline__ void load_tiles(
    const __half* __restrict__ A, const __half* __restrict__ B, int Kdim,
    int bm, int bn, __half* As, __half* Bs, int stg, int k0, int tid) {
#pragma unroll
    for (int t = 0; t < 4; t++) {
        int v = tid + t * 256;
        int r = v >> 3;
        int c = (v & 7) * 8;
        cp16(&As[stg * BUFH + r * KSTR + c], &A[(size_t)(bm + r) * Kdim + k0 + c]);
        cp16(&Bs[stg * BUFH + r * KSTR + c], &B[(size_t)(bn + r) * Kdim + k0 + c]);
    }
    cp_commit();
}

__device__ __forceinline__ void gemm_mainloop(
    const __half* __restrict__ A, const __half* __restrict__ B, int Kdim,
    int bm, int bn, __half* As, __half* Bs,
    wmma::fragment<wmma::accumulator, 16, 16, 16, float> acc[4][2],
    int tid, int wr, int wc) {
    const int KT = Kdim / BK;
    load_tiles(A, B, Kdim, bm, bn, As, Bs, 0, 0, tid);
    load_tiles(A, B, Kdim, bm, bn, As, Bs, 1, BK, tid);
    int stg = 0;
    for (int kt = 0; kt < KT; ++kt) {
        cp_wait<1>();
        __syncthreads();
        const __half* Ab = &As[stg * BUFH];
        const __half* Bb = &Bs[stg * BUFH];
#pragma unroll
        for (int kk = 0; kk < BK; kk += 16) {
            wmma::fragment<wmma::matrix_a, 16, 16, 16, __half, wmma::row_major> af[4];
            wmma::fragment<wmma::matrix_b, 16, 16, 16, __half, wmma::col_major> bf[2];
#pragma unroll
            for (int i = 0; i < 4; i++)
                wmma::load_matrix_sync(af[i], &Ab[(wr * 64 + i * 16) * KSTR + kk], KSTR);
#pragma unroll
            for (int j = 0; j < 2; j++)
                wmma::load_matrix_sync(bf[j], &Bb[(wc * 32 + j * 16) * KSTR + kk], KSTR);
#pragma unroll
            for (int i = 0; i < 4; i++)
#pragma unroll
                for (int j = 0; j < 2; j++)
                    wmma::mma_sync(acc[i][j], af[i], bf[j], acc[i][j]);
        }
        if (kt + 2 < KT) {
            int ns = stg + 2; if (ns >= NSTG) ns -= NSTG;
            load_tiles(A, B, Kdim, bm, bn, As, Bs, ns, (kt + 2) * BK, tid);
        } else {
            cp_commit();
        }
        if (++stg == NSTG) stg = 0;
    }
}

// ---------------- fused QKV projection (direct split-head fp16 epilogue) ----------------
__global__ __launch_bounds__(256) void gemm_qkv_kernel(
    const __half* __restrict__ X,
    const __half* __restrict__ Wq, const __half* __restrict__ Wk, const __half* __restrict__ Wv,
    __half* __restrict__ Q, __half* __restrict__ K, __half* __restrict__ V) {
    extern __shared__ char smem[];
    __half* As = (__half*)smem;
    __half* Bs = As + NSTG * BUFH;

    const __half* Bw = (blockIdx.z == 0) ? Wq : (blockIdx.z == 1) ? Wk : Wv;
    __half* O = (blockIdx.z == 0) ? Q : (blockIdx.z == 1) ? K : V;

    const int tid = threadIdx.x, warp = tid >> 5;
    const int wr = warp >> 2, wc = warp & 3;
    const int bm = blockIdx.y * 128, bn = blockIdx.x * 128;

    wmma::fragment<wmma::accumulator, 16, 16, 16, float> acc[4][2];
#pragma unroll
    for (int i = 0; i < 4; i++)
#pragma unroll
        for (int j = 0; j < 2; j++) wmma::fill_fragment(acc[i][j], 0.0f);

    gemm_mainloop(X, Bw, DMv, bm, bn, As, Bs, acc, tid, wr, wc);

    float* Cs = (float*)smem;  // 128 x 132
    __syncthreads();
#pragma unroll
    for (int i = 0; i < 4; i++)
#pragma unroll
        for (int j = 0; j < 2; j++)
            wmma::store_matrix_sync(&Cs[(wr * 64 + i * 16) * 132 + wc * 32 + j * 16],
                                    acc[i][j], 132, wmma::mem_row_major);
    __syncthreads();

    const int b = bm >> 11, s0 = bm & (Sv - 1), h = blockIdx.x;
    __half* Ob = O + (((size_t)(b * Hv + h)) * Sv + s0) * DKv;
    for (int i = tid; i < 128 * 128; i += 256) {
        int r = i >> 7, d = i & 127;
        Ob[r * DKv + d] = __float2half(Cs[r * 132 + d]);
    }
}

// ---------------- output projection GEMM (f32 out) ----------------
__global__ __launch_bounds__(256) void gemm_out_kernel(
    const __half* __restrict__ A, const __half* __restrict__ Bw, float* __restrict__ C) {
    extern __shared__ char smem[];
    __half* As = (__half*)smem;
    __half* Bs = As + NSTG * BUFH;

    const int tid = threadIdx.x, warp = tid >> 5;
    const int wr = warp >> 2, wc = warp & 3;
    const int bm = blockIdx.y * 128, bn = blockIdx.x * 128;

    wmma::fragment<wmma::accumulator, 16, 16, 16, float> acc[4][2];
#pragma unroll
    for (int i = 0; i < 4; i++)
#pragma unroll
        for (int j = 0; j < 2; j++) wmma::fill_fragment(acc[i][j], 0.0f);

    gemm_mainloop(A, Bw, DMv, bm, bn, As, Bs, acc, tid, wr, wc);

#pragma unroll
    for (int i = 0; i < 4; i++)
#pragma unroll
        for (int j = 0; j < 2; j++) {
            float* cptr = &C[(size_t)(bm + wr * 64 + i * 16) * DMv + bn + wc * 32 + j * 16];
            wmma::store_matrix_sync(cptr, acc[i][j], DMv, wmma::mem_row_major);
        }
}

// ---------------- flash attention v2: warp-private softmax, O in registers ----------------
// Grid (S/64, B*H), 128 threads (4 warps). Each warp owns 16 query rows end-to-end.
// Block barriers only around the shared K/V tiles (2 per kb iteration).
#define QSTR 136
#define SSTR 68
#define PSTR 72
#define OSTR 132

#define FLASH_SMEM (3 * 64 * QSTR * 2 /*Q,K,V*/ + 64 * SSTR * 4 /*Sc*/ + \
                    64 * PSTR * 2 /*P*/ + 64 * OSTR * 4 /*Ts*/)

__global__ __launch_bounds__(128, 2) void flash_kernel(
    const __half* __restrict__ Q, const __half* __restrict__ K,
    const __half* __restrict__ V, __half* __restrict__ Ch,
    const int* __restrict__ um_ptr) {
    extern __shared__ char smem[];
    __half* Qs = (__half*)smem;            // 64 x QSTR
    __half* Ks = Qs + 64 * QSTR;
    __half* Vs = Ks + 64 * QSTR;
    float*  Sc = (float*)(Vs + 64 * QSTR); // 64 x SSTR (per-warp 16-row slices)
    __half* Ps = (__half*)(Sc + 64 * SSTR);// 64 x PSTR (per-warp slices)
    float*  Ts = (float*)(Ps + 64 * PSTR); // 64 x OSTR (per-warp slices)

    const int tid  = threadIdx.x;
    const int warp = tid >> 5;
    const int lane = tid & 31;
    const int qb = blockIdx.x;
    const int bh = blockIdx.y;
    const int um = *um_ptr;

    const int riw = lane >> 1;             // row in warp 0..15
    const int hf  = lane & 1;              // half-row selector
    const int my_row = warp * 16 + riw;    // 0..63 within tile
    const int qg = qb * 64 + my_row;       // global query index

    // load Q tile (64 x 128)
    const __half* Qbase = Q + ((size_t)bh * Sv + qb * 64) * DKv;
#pragma unroll
    for (int t = 0; t < 8; t++) {
        int v = tid + t * 128;
        int r = v >> 4, c = (v & 15) * 8;
        *(uint4*)&Qs[r * QSTR + c] = *(const uint4*)&Qbase[r * DKv + c];
    }

    float O[64];
#pragma unroll
    for (int j = 0; j < 64; j++) O[j] = 0.0f;
    float m_r = -1e30f, l_r = 0.0f;

    const int kb_end = um ? qb : (Sv / 64 - 1);
    const float scale = 0.08838834764831845f;  // 1/sqrt(128)

    for (int kb = 0; kb <= kb_end; ++kb) {
        const __half* Kbase = K + ((size_t)bh * Sv + kb * 64) * DKv;
        const __half* Vbase = V + ((size_t)bh * Sv + kb * 64) * DKv;
#pragma unroll
        for (int t = 0; t < 8; t++) {
            int v = tid + t * 128;
            int r = v >> 4, c = (v & 15) * 8;
            *(uint4*)&Ks[r * QSTR + c] = *(const uint4*)&Kbase[r * DKv + c];
            *(uint4*)&Vs[r * QSTR + c] = *(const uint4*)&Vbase[r * DKv + c];
        }
        __syncthreads();   // KV (and Q on first iter) visible to all warps

        // S = Q * K^T  (warp-private: 16 rows x 64 keys)
        {
            wmma::fragment<wmma::accumulator, 16, 16, 16, float> sacc[4];
#pragma unroll
            for (int j = 0; j < 4; j++) wmma::fill_fragment(sacc[j], 0.0f);
#pragma unroll
            for (int kk = 0; kk < DKv; kk += 16) {
                wmma::fragment<wmma::matrix_a, 16, 16, 16, __half, wmma::row_major> qa;
                wmma::load_matrix_sync(qa, &Qs[(warp * 16) * QSTR + kk], QSTR);
#pragma unroll
                for (int j = 0; j < 4; j++) {
                    wmma::fragment<wmma::matrix_b, 16, 16, 16, __half, wmma::col_major> kf;
                    wmma::load_matrix_sync(kf, &Ks[(j * 16) * QSTR + kk], QSTR);
                    wmma::mma_sync(sacc[j], qa, kf, sacc[j]);
                }
            }
#pragma unroll
            for (int j = 0; j < 4; j++)
                wmma::store_matrix_sync(&Sc[(warp * 16) * SSTR + j * 16], sacc[j], SSTR,
                                        wmma::mem_row_major);
        }
        __syncwarp();

        // softmax: lane owns row riw, score cols [hf*32, hf*32+32)
        float alpha;
        {
            float vals[32];
            float lmax = -1e30f;
#pragma unroll
            for (int c = 0; c < 32; c++) {
                int kc = hf * 32 + c;
                float v = Sc[(warp * 16 + riw) * SSTR + kc] * scale;
                if (um && (kb * 64 + kc) > qg) v = -1e30f;
                vals[c] = v;
                lmax = fmaxf(lmax, v);
            }
            lmax = fmaxf(lmax, __shfl_xor_sync(0xffffffffu, lmax, 1));
            float mn = fmaxf(m_r, lmax);
            alpha = __expf(m_r - mn);
            float lsum = 0.0f;
#pragma unroll
            for (int c = 0; c < 32; c++) {
                float p = __expf(vals[c] - mn);
                lsum += p;
                Ps[(warp * 16 + riw) * PSTR + hf * 32 + c] = __float2half(p);
            }
            lsum += __shfl_xor_sync(0xffffffffu, lsum, 1);
            l_r = l_r * alpha + lsum;
            m_r = mn;
        }
        __syncwarp();

        // T = P * V  (warp-private rows; V shared read-only)
        {
            wmma::fragment<wmma::accumulator, 16, 16, 16, float> oacc[8];
#pragma unroll
            for (int j = 0; j < 8; j++) wmma::fill_fragment(oacc[j], 0.0f);
#pragma unroll
            for (int kk = 0; kk < 64; kk += 16) {
                wmma::fragment<wmma::matrix_a, 16, 16, 16, __half, wmma::row_major> pa;
                wmma::load_matrix_sync(pa, &Ps[(warp * 16) * PSTR + kk], PSTR);
#pragma unroll
                for (int j = 0; j < 8; j++) {
                    wmma::fragment<wmma::matrix_b, 16, 16, 16, __half, wmma::row_major> vb;
                    wmma::load_matrix_sync(vb, &Vs[kk * QSTR + j * 16], QSTR);
                    wmma::mma_sync(oacc[j], pa, vb, oacc[j]);
                }
            }
#pragma unroll
            for (int j = 0; j < 8; j++)
                wmma::store_matrix_sync(&Ts[(warp * 16) * OSTR + j * 16], oacc[j], OSTR,
                                        wmma::mem_row_major);
        }
        __syncwarp();

        // O accumulate in registers: lane owns row riw, O cols [hf*64, hf*64+64)
        {
            const float* tr = &Ts[(warp * 16 + riw) * OSTR + hf * 64];
#pragma unroll
            for (int j = 0; j < 64; j++) O[j] = O[j] * alpha + tr[j];
        }
        __syncthreads();   // all warps done with Ks/Vs before next overwrite
    }

    // epilogue: ctx fp16, heads merged back to [B, S, H*DK]
    const int b = bh / Hv, h = bh % Hv;
    const float inv = 1.0f / l_r;
    __half* obase = Ch + (size_t)(b * Sv + qb * 64 + my_row) * DMv + h * DKv + hf * 64;
#pragma unroll
    for (int j0 = 0; j0 < 64; j0 += 8) {
        __half2 p0 = __floats2half2_rn(O[j0 + 0] * inv, O[j0 + 1] * inv);
        __half2 p1 = __floats2half2_rn(O[j0 + 2] * inv, O[j0 + 3] * inv);
        __half2 p2 = __floats2half2_rn(O[j0 + 4] * inv, O[j0 + 5] * inv);
        __half2 p3 = __floats2half2_rn(O[j0 + 6] * inv, O[j0 + 7] * inv);
        uint4 o;
        o.x = *(unsigned int*)&p0; o.y = *(unsigned int*)&p1;
        o.z = *(unsigned int*)&p2; o.w = *(unsigned int*)&p3;
        *(uint4*)&obase[j0] = o;
    }
}

// ---------------- launch ----------------
extern "C" void kernel_launch(void* const* d_in, const int* in_sizes, int n_in,
                              void* d_out, int out_size) {
    const float* x  = (const float*)d_in[0];
    const float* Wq = (const float*)d_in[1];
    const float* Wk = (const float*)d_in[2];
    const float* Wv = (const float*)d_in[3];
    const float* Wo = (const float*)d_in[4];
    const int*   um = (const int*)d_in[5];
    float* out = (float*)d_out;

    __half *Xh, *Wqh, *Wkh, *Wvh, *Woh, *Q, *K, *V, *Ch;
    cudaGetSymbolAddress((void**)&Xh,  g_Xh);
    cudaGetSymbolAddress((void**)&Wqh, g_Wqh);
    cudaGetSymbolAddress((void**)&Wkh, g_Wkh);
    cudaGetSymbolAddress((void**)&Wvh, g_Wvh);
    cudaGetSymbolAddress((void**)&Woh, g_Woh);
    cudaGetSymbolAddress((void**)&Q,   g_Q);
    cudaGetSymbolAddress((void**)&K,   g_K);
    cudaGetSymbolAddress((void**)&V,   g_V);
    cudaGetSymbolAddress((void**)&Ch,  g_Ch);

    f2h_kernel<<<2048, 256>>>((const float4*)x,  (uint4*)Xh,  Mv * DMv / 8);
    f2h_kernel<<<1024, 256>>>((const float4*)Wq, (uint4*)Wqh, DMv * DMv / 8);
    f2h_kernel<<<1024, 256>>>((const float4*)Wk, (uint4*)Wkh, DMv * DMv / 8);
    f2h_kernel<<<1024, 256>>>((const float4*)Wv, (uint4*)Wvh, DMv * DMv / 8);
    f2h_kernel<<<1024, 256>>>((const float4*)Wo, (uint4*)Woh, DMv * DMv / 8);

    cudaFuncSetAttribute(gemm_qkv_kernel, cudaFuncAttributeMaxDynamicSharedMemorySize, GEMM_SMEM);
    cudaFuncSetAttribute(gemm_out_kernel, cudaFuncAttributeMaxDynamicSharedMemorySize, GEMM_SMEM);
    cudaFuncSetAttribute(flash_kernel, cudaFuncAttributeMaxDynamicSharedMemorySize, FLASH_SMEM);

    gemm_qkv_kernel<<<dim3(16, 64, 3), 256, GEMM_SMEM>>>(Xh, Wqh, Wkh, Wvh, Q, K, V);

    flash_kernel<<<dim3(Sv / 64, Bv * Hv), 128, FLASH_SMEM>>>(Q, K, V, Ch, um);

    gemm_out_kernel<<<dim3(16, 64), 256, GEMM_SMEM>>>(Ch, Woh, out);
}